// round 8
// baseline (speedup 1.0000x reference)
#include <cuda_runtime.h>
#include <math.h>

#define NTOT 2048          // B*N
#define KSEL 20

__device__ float  g_part[4 * NTOT * 512]; // K-split partial GEMM results
__device__ float  g_xlxr[NTOT * 512];     // [g][0:256)=xl, [256:512)=xr
__device__ float  g_xrT[4 * 256 * 512];   // [b][d][j] transposed xr
__device__ float  g_L[NTOT];
__device__ float  g_R[NTOT];

// ---------------- packed f32x2 helpers ----------------
__device__ __forceinline__ double fma2(double a, double b, double c) {
    double d;
    asm("fma.rn.f32x2 %0, %1, %2, %3;" : "=d"(d) : "d"(a), "d"(b), "d"(c));
    return d;
}
__device__ __forceinline__ double add2(double a, double b) {
    double d;
    asm("add.rn.f32x2 %0, %1, %2;" : "=d"(d) : "d"(a), "d"(b));
    return d;
}
__device__ __forceinline__ double abs2(double a) {
    return __longlong_as_double(__double_as_longlong(a) & 0x7fffffff7fffffffULL);
}
__device__ __forceinline__ double dup2(float v) {
    double d;
    asm("mov.b64 %0, {%1, %1};" : "=d"(d) : "f"(v));
    return d;
}
__device__ __forceinline__ float2 unpack2(double a) {
    float2 f;
    asm("mov.b64 {%0, %1}, %2;" : "=f"(f.x), "=f"(f.y) : "d"(a));
    return f;
}

// ---------------------------------------------------------------------------
// Kernel 1: K-split-4 projection GEMM. Tile 128(M) x 64(N), BK=16, K=64/block,
// 256 threads, per-thread 8x4 (2 f32x2 pairs), A scalar-broadcast + reg-dup.
// grid (16, 8, 4) = 512 blocks -> ~3.4 blocks/SM.
// ---------------------------------------------------------------------------
__global__ __launch_bounds__(256, 3) void proj_kernel(
    const float* __restrict__ x,
    const float* __restrict__ Wl, const float* __restrict__ bl,
    const float* __restrict__ Wr, const float* __restrict__ br)
{
    __shared__ __align__(16) float As[2][16 * 132];  // [k][m], m=128 (+pad)
    __shared__ __align__(16) float Bs[2][16 * 68];   // [k][n], n=64 (+pad)
    const int tid = threadIdx.x;
    const int tx = tid & 15;          // N direction (4 cols each)
    const int ty = tid >> 4;          // M direction (8 rows each)
    const int g0 = blockIdx.x * 128;
    const int n0 = blockIdx.y * 64;
    const int kh = blockIdx.z;        // K quarter
    const float* W    = (n0 < 256) ? Wl : Wr;
    const float* bias = (n0 < 256) ? bl : br;
    const int nw0 = (n0 < 256) ? n0 : n0 - 256;

    const int lmA = tid >> 1;             // 0..127
    const int lkA = (tid & 1) * 8;        // 0 or 8
    const int lmB = tid >> 2;             // 0..63
    const int lkB = (tid & 3) * 4;        // 0,4,8,12

    const float* xp = &x[(g0 + lmA) * 256 + kh * 64 + lkA];
    const float* wp = &W[(nw0 + lmB) * 256 + kh * 64 + lkB];

    double acc[8][2];
#pragma unroll
    for (int i = 0; i < 8; ++i) { acc[i][0] = 0.0; acc[i][1] = 0.0; }

    float4 a0 = *(const float4*)xp;
    float4 a1 = *(const float4*)(xp + 4);
    float4 bv = *(const float4*)wp;
    {
        float* A = As[0]; float* B = Bs[0];
        A[(lkA + 0) * 132 + lmA] = a0.x; A[(lkA + 1) * 132 + lmA] = a0.y;
        A[(lkA + 2) * 132 + lmA] = a0.z; A[(lkA + 3) * 132 + lmA] = a0.w;
        A[(lkA + 4) * 132 + lmA] = a1.x; A[(lkA + 5) * 132 + lmA] = a1.y;
        A[(lkA + 6) * 132 + lmA] = a1.z; A[(lkA + 7) * 132 + lmA] = a1.w;
        B[(lkB + 0) * 68 + lmB] = bv.x;  B[(lkB + 1) * 68 + lmB] = bv.y;
        B[(lkB + 2) * 68 + lmB] = bv.z;  B[(lkB + 3) * 68 + lmB] = bv.w;
    }
    a0 = *(const float4*)(xp + 16);
    a1 = *(const float4*)(xp + 20);
    bv = *(const float4*)(wp + 16);

#pragma unroll 1
    for (int t = 0; t < 4; ++t) {
        __syncthreads();
        if (t < 3) {
            float* A = As[(t + 1) & 1]; float* B = Bs[(t + 1) & 1];
            A[(lkA + 0) * 132 + lmA] = a0.x; A[(lkA + 1) * 132 + lmA] = a0.y;
            A[(lkA + 2) * 132 + lmA] = a0.z; A[(lkA + 3) * 132 + lmA] = a0.w;
            A[(lkA + 4) * 132 + lmA] = a1.x; A[(lkA + 5) * 132 + lmA] = a1.y;
            A[(lkA + 6) * 132 + lmA] = a1.z; A[(lkA + 7) * 132 + lmA] = a1.w;
            B[(lkB + 0) * 68 + lmB] = bv.x;  B[(lkB + 1) * 68 + lmB] = bv.y;
            B[(lkB + 2) * 68 + lmB] = bv.z;  B[(lkB + 3) * 68 + lmB] = bv.w;
        }
        if (t < 2) {
            a0 = *(const float4*)(xp + (t + 2) * 16);
            a1 = *(const float4*)(xp + (t + 2) * 16 + 4);
            bv = *(const float4*)(wp + (t + 2) * 16);
        }
        const float* A = As[t & 1]; const float* B = Bs[t & 1];
#pragma unroll
        for (int k = 0; k < 16; ++k) {
            const float4 r0 = *(const float4*)&A[k * 132 + ty * 8];
            const float4 r1 = *(const float4*)&A[k * 132 + ty * 8 + 4];
            const double2 b2 = *(const double2*)&B[k * 68 + tx * 4];
            double d;
            d = dup2(r0.x); acc[0][0] = fma2(d, b2.x, acc[0][0]);
                            acc[0][1] = fma2(d, b2.y, acc[0][1]);
            d = dup2(r0.y); acc[1][0] = fma2(d, b2.x, acc[1][0]);
                            acc[1][1] = fma2(d, b2.y, acc[1][1]);
            d = dup2(r0.z); acc[2][0] = fma2(d, b2.x, acc[2][0]);
                            acc[2][1] = fma2(d, b2.y, acc[2][1]);
            d = dup2(r0.w); acc[3][0] = fma2(d, b2.x, acc[3][0]);
                            acc[3][1] = fma2(d, b2.y, acc[3][1]);
            d = dup2(r1.x); acc[4][0] = fma2(d, b2.x, acc[4][0]);
                            acc[4][1] = fma2(d, b2.y, acc[4][1]);
            d = dup2(r1.y); acc[5][0] = fma2(d, b2.x, acc[5][0]);
                            acc[5][1] = fma2(d, b2.y, acc[5][1]);
            d = dup2(r1.z); acc[6][0] = fma2(d, b2.x, acc[6][0]);
                            acc[6][1] = fma2(d, b2.y, acc[6][1]);
            d = dup2(r1.w); acc[7][0] = fma2(d, b2.x, acc[7][0]);
                            acc[7][1] = fma2(d, b2.y, acc[7][1]);
        }
    }

    float* dst = g_part + (size_t)kh * NTOT * 512;
#pragma unroll
    for (int i = 0; i < 8; ++i) {
        const int row = g0 + ty * 8 + i;
        const float2 p0 = unpack2(acc[i][0]);
        const float2 p1 = unpack2(acc[i][1]);
        float4 o;
        if (kh == 0) {
            o.x = p0.x + bias[nw0 + tx * 4 + 0];
            o.y = p0.y + bias[nw0 + tx * 4 + 1];
            o.z = p1.x + bias[nw0 + tx * 4 + 2];
            o.w = p1.y + bias[nw0 + tx * 4 + 3];
        } else {
            o.x = p0.x; o.y = p0.y; o.z = p1.x; o.w = p1.y;
        }
        *(float4*)&dst[row * 512 + n0 + tx * 4] = o;
    }
}

// ---------------------------------------------------------------------------
// Kernel 2: finalize. Sum 4 K-partials -> g_xlxr; L/R dots; xr transpose g_xrT.
// ---------------------------------------------------------------------------
#define SLAB_S 524
#define FIN_SMEM ((32 * SLAB_S + 256) * 4)

__global__ __launch_bounds__(256) void finalize_kernel(const float* __restrict__ att)
{
    extern __shared__ float sh[];
    float* slab  = sh;                 // [32][SLAB_S]
    float* att_s = sh + 32 * SLAB_S;   // [256]
    const int tid = threadIdx.x;
    const int g0 = blockIdx.x * 32;
    const int b = g0 >> 9;
    const int j0b = g0 & 511;

    att_s[tid] = att[tid];
#pragma unroll
    for (int p = 0; p < 16; ++p) {
        const int idx = p * 256 + tid;
        const int row = idx >> 7, c4 = idx & 127;
        const size_t ga = (size_t)(g0 + row) * 512 + c4 * 4;
        float4 a = *(const float4*)&g_part[ga];
#pragma unroll
        for (int q = 1; q < 4; ++q) {
            const float4 c = *(const float4*)&g_part[(size_t)q * NTOT * 512 + ga];
            a.x += c.x; a.y += c.y; a.z += c.z; a.w += c.w;
        }
        *(float4*)&g_xlxr[ga] = a;
        *(float4*)&slab[row * SLAB_S + c4 * 4] = a;
    }
    __syncthreads();

    const int w = tid >> 5, l = tid & 31;
#pragma unroll
    for (int p = 0; p < 8; ++p) {
        const int id = p * 8 + w;
        const int row = id >> 1, half = id & 1;
        float s = 0.f;
#pragma unroll
        for (int q = 0; q < 8; ++q)
            s += att_s[l + 32 * q] * slab[row * SLAB_S + half * 256 + l + 32 * q];
#pragma unroll
        for (int off = 16; off; off >>= 1) s += __shfl_xor_sync(0xffffffffu, s, off);
        if (l == 0) {
            if (half) g_R[g0 + row] = 0.6f * s;
            else      g_L[g0 + row] = 0.6f * s;
        }
    }

    // transpose xr half -> g_xrT[b][d][j]
#pragma unroll
    for (int p = 0; p < 32; ++p) {
        const int idx = p * 256 + tid;      // 0..8191
        const int d = idx >> 5, jl = idx & 31;
        g_xrT[((size_t)b * 256 + d) * 512 + j0b + jl] = slab[jl * SLAB_S + 256 + d];
    }
}

// ---------------------------------------------------------------------------
// Kernel 3: FUSED pairwise scores + top-20 + softmax.
// 128 threads, 4 i-rows, grid 512 (~3.4 blocks/SM). Thread owns j-pairs
// {tid, tid+128} x 4 rows = 8 register accumulators. alpha -> smem -> topk
// by all 4 warps (1 row each).
// ---------------------------------------------------------------------------
__global__ __launch_bounds__(128, 5) void pairtop_kernel(const float* __restrict__ att,
                                                         float* __restrict__ out)
{
    __shared__ double xl2d[256 * 4];   // [d][r] dup'd xl, 8KB
    __shared__ double ws2[256];        // dup'd 0.4*att, 2KB
    __shared__ float  alpha_s[4 * 512];
    __shared__ float  Ls[4];

    const int tid = threadIdx.x;
    const int g0 = blockIdx.x * 4;
    const int b512 = g0 & ~511;
    const int b = b512 >> 9;

    ws2[tid]       = dup2(0.4f * att[tid]);
    ws2[tid + 128] = dup2(0.4f * att[tid + 128]);
    if (tid < 4) Ls[tid] = g_L[g0 + tid];
#pragma unroll
    for (int q = 0; q < 8; ++q) {
        const int idx = q * 128 + tid;     // 0..1023
        const int r = idx & 3, d = idx >> 2;
        xl2d[d * 4 + r] = dup2(g_xlxr[(size_t)(g0 + r) * 512 + d]);
    }
    __syncthreads();

    const int jp0 = tid;                   // j-pairs owned by this thread
    const int jp1 = tid + 128;
    const double* __restrict__ xrp =
        (const double*)g_xrT + (size_t)b * 256 * 256;
    const float2 Rj0 = *(const float2*)&g_R[b512 + 2 * jp0];
    const float2 Rj1 = *(const float2*)&g_R[b512 + 2 * jp1];

    double acc[8];                         // [row][jp]: acc[2r], acc[2r+1]
#pragma unroll
    for (int i = 0; i < 8; ++i) acc[i] = 0.0;

#pragma unroll 1
    for (int c = 0; c < 64; ++c) {         // 4 d per chunk
        double xr0[4], xr1[4];
#pragma unroll
        for (int q = 0; q < 4; ++q) {
            xr0[q] = xrp[(size_t)(c * 4 + q) * 256 + jp0];
            xr1[q] = xrp[(size_t)(c * 4 + q) * 256 + jp1];
        }
#pragma unroll
        for (int q = 0; q < 4; ++q) {
            const int d = c * 4 + q;
            const double wsd = ws2[d];
            const double2 x01 = *(const double2*)&xl2d[d * 4 + 0];
            const double2 x23 = *(const double2*)&xl2d[d * 4 + 2];
            acc[0] = fma2(wsd, abs2(add2(x01.x, xr0[q])), acc[0]);
            acc[1] = fma2(wsd, abs2(add2(x01.x, xr1[q])), acc[1]);
            acc[2] = fma2(wsd, abs2(add2(x01.y, xr0[q])), acc[2]);
            acc[3] = fma2(wsd, abs2(add2(x01.y, xr1[q])), acc[3]);
            acc[4] = fma2(wsd, abs2(add2(x23.x, xr0[q])), acc[4]);
            acc[5] = fma2(wsd, abs2(add2(x23.x, xr1[q])), acc[5]);
            acc[6] = fma2(wsd, abs2(add2(x23.y, xr0[q])), acc[6]);
            acc[7] = fma2(wsd, abs2(add2(x23.y, xr1[q])), acc[7]);
        }
    }
#pragma unroll
    for (int r = 0; r < 4; ++r) {
        const float2 f0 = unpack2(acc[2 * r]);
        const float2 f1 = unpack2(acc[2 * r + 1]);
        *(float2*)&alpha_s[r * 512 + 2 * jp0] =
            make_float2(Ls[r] + Rj0.x + f0.x, Ls[r] + Rj0.y + f0.y);
        *(float2*)&alpha_s[r * 512 + 2 * jp1] =
            make_float2(Ls[r] + Rj1.x + f1.x, Ls[r] + Rj1.y + f1.y);
    }
    __syncthreads();

    // ---- top-20 + softmax: warp w handles row w (4 warps, 4 rows) ----
    const int w = tid >> 5, l = tid & 31;
    const float* arow = &alpha_s[w * 512];
    float v[16];
#pragma unroll
    for (int t = 0; t < 16; ++t) v[t] = arow[l + 32 * t];

    float wv = 0.f; int wj = 0;
    for (int kk = 0; kk < KSEL; ++kk) {
        float bv = -INFINITY; int bt = 0;
#pragma unroll
        for (int t = 0; t < 16; ++t)
            if (v[t] > bv) { bv = v[t]; bt = t; }   // strict > keeps lowest j
        int bj = bt * 32 + l;
#pragma unroll
        for (int off = 16; off; off >>= 1) {
            const float ov = __shfl_xor_sync(0xffffffffu, bv, off);
            const int   oj = __shfl_xor_sync(0xffffffffu, bj, off);
            if (ov > bv || (ov == bv && oj < bj)) { bv = ov; bj = oj; }
        }
        if (l == kk) { wv = bv; wj = bj; }
        const int owner = bj & 31, slot = bj >> 5;
        if (l == owner) {
#pragma unroll
            for (int t = 0; t < 16; ++t)
                if (slot == t) v[t] = -INFINITY;
        }
    }

    const float m = __shfl_sync(0xffffffffu, wv, 0);   // largest selected
    const float e = (l < KSEL) ? expf(wv - m) : 0.f;
    float s = e;
#pragma unroll
    for (int off = 16; off; off >>= 1) s += __shfl_xor_sync(0xffffffffu, s, off);
    if (l < KSEL) {
        const int g = g0 + w;
        const int base = g * KSEL + l;
        out[base]                   = (float)g;             // index_i
        out[NTOT * KSEL + base]     = (float)(b512 + wj);   // index_j
        out[2 * NTOT * KSEL + base] = e / s;                // attention
    }
}

// ---------------------------------------------------------------------------
extern "C" void kernel_launch(void* const* d_in, const int* in_sizes, int n_in,
                              void* d_out, int out_size)
{
    const float* x   = (const float*)d_in[0];
    const float* Wl  = (const float*)d_in[3];
    const float* bl  = (const float*)d_in[4];
    const float* Wr  = (const float*)d_in[5];
    const float* br  = (const float*)d_in[6];
    const float* att = (const float*)d_in[7];
    float* out = (float*)d_out;

    proj_kernel<<<dim3(16, 8, 4), 256>>>(x, Wl, bl, Wr, br);
    cudaFuncSetAttribute(finalize_kernel,
                         cudaFuncAttributeMaxDynamicSharedMemorySize, FIN_SMEM);
    finalize_kernel<<<64, 256, FIN_SMEM>>>(att);
    pairtop_kernel<<<512, 128>>>(att, out);
}

// round 9
// speedup vs baseline: 1.0346x; 1.0346x over previous
#include <cuda_runtime.h>
#include <math.h>

#define NTOT 2048          // B*N
#define KSEL 20

__device__ float  g_part[2 * NTOT * 512]; // K-split partial GEMM results
__device__ float  g_xlxr[NTOT * 512];     // [g][0:256)=xl, [256:512)=xr
__device__ float  g_xrT[4 * 256 * 512];   // [b][d][j] transposed xr
__device__ float  g_L[NTOT];
__device__ float  g_R[NTOT];

// ---------------- packed f32x2 helpers ----------------
__device__ __forceinline__ double fma2(double a, double b, double c) {
    double d;
    asm("fma.rn.f32x2 %0, %1, %2, %3;" : "=d"(d) : "d"(a), "d"(b), "d"(c));
    return d;
}
__device__ __forceinline__ double add2(double a, double b) {
    double d;
    asm("add.rn.f32x2 %0, %1, %2;" : "=d"(d) : "d"(a), "d"(b));
    return d;
}
__device__ __forceinline__ double abs2(double a) {
    return __longlong_as_double(__double_as_longlong(a) & 0x7fffffff7fffffffULL);
}
__device__ __forceinline__ double dup2(float v) {
    double d;
    asm("mov.b64 %0, {%1, %1};" : "=d"(d) : "f"(v));
    return d;
}
__device__ __forceinline__ float2 unpack2(double a) {
    float2 f;
    asm("mov.b64 {%0, %1}, %2;" : "=f"(f.x), "=f"(f.y) : "d"(a));
    return f;
}

// ---------------------------------------------------------------------------
// Kernel 1: K-split-2 projection GEMM. Tile 128(M) x 64(N), BK=16, K=128/blk,
// 256 threads, per-thread 8x4 (2 f32x2 pairs), A scalar-broadcast + reg-dup.
// grid (16, 8, 2) = 256 blocks.
// ---------------------------------------------------------------------------
__global__ __launch_bounds__(256, 3) void proj_kernel(
    const float* __restrict__ x,
    const float* __restrict__ Wl, const float* __restrict__ bl,
    const float* __restrict__ Wr, const float* __restrict__ br)
{
    __shared__ __align__(16) float As[2][16 * 132];  // [k][m], m=128 (+pad)
    __shared__ __align__(16) float Bs[2][16 * 68];   // [k][n], n=64 (+pad)
    const int tid = threadIdx.x;
    const int tx = tid & 15;          // N direction (4 cols each)
    const int ty = tid >> 4;          // M direction (8 rows each)
    const int g0 = blockIdx.x * 128;
    const int n0 = blockIdx.y * 64;
    const int kh = blockIdx.z;        // K half
    const float* W    = (n0 < 256) ? Wl : Wr;
    const float* bias = (n0 < 256) ? bl : br;
    const int nw0 = (n0 < 256) ? n0 : n0 - 256;

    const int lmA = tid >> 1;             // 0..127
    const int lkA = (tid & 1) * 8;        // 0 or 8
    const int lmB = tid >> 2;             // 0..63
    const int lkB = (tid & 3) * 4;        // 0,4,8,12

    const float* xp = &x[(g0 + lmA) * 256 + kh * 128 + lkA];
    const float* wp = &W[(nw0 + lmB) * 256 + kh * 128 + lkB];

    double acc[8][2];
#pragma unroll
    for (int i = 0; i < 8; ++i) { acc[i][0] = 0.0; acc[i][1] = 0.0; }

    float4 a0 = *(const float4*)xp;
    float4 a1 = *(const float4*)(xp + 4);
    float4 bv = *(const float4*)wp;
    {
        float* A = As[0]; float* B = Bs[0];
        A[(lkA + 0) * 132 + lmA] = a0.x; A[(lkA + 1) * 132 + lmA] = a0.y;
        A[(lkA + 2) * 132 + lmA] = a0.z; A[(lkA + 3) * 132 + lmA] = a0.w;
        A[(lkA + 4) * 132 + lmA] = a1.x; A[(lkA + 5) * 132 + lmA] = a1.y;
        A[(lkA + 6) * 132 + lmA] = a1.z; A[(lkA + 7) * 132 + lmA] = a1.w;
        B[(lkB + 0) * 68 + lmB] = bv.x;  B[(lkB + 1) * 68 + lmB] = bv.y;
        B[(lkB + 2) * 68 + lmB] = bv.z;  B[(lkB + 3) * 68 + lmB] = bv.w;
    }
    a0 = *(const float4*)(xp + 16);
    a1 = *(const float4*)(xp + 20);
    bv = *(const float4*)(wp + 16);

#pragma unroll 1
    for (int t = 0; t < 8; ++t) {
        __syncthreads();
        if (t < 7) {
            float* A = As[(t + 1) & 1]; float* B = Bs[(t + 1) & 1];
            A[(lkA + 0) * 132 + lmA] = a0.x; A[(lkA + 1) * 132 + lmA] = a0.y;
            A[(lkA + 2) * 132 + lmA] = a0.z; A[(lkA + 3) * 132 + lmA] = a0.w;
            A[(lkA + 4) * 132 + lmA] = a1.x; A[(lkA + 5) * 132 + lmA] = a1.y;
            A[(lkA + 6) * 132 + lmA] = a1.z; A[(lkA + 7) * 132 + lmA] = a1.w;
            B[(lkB + 0) * 68 + lmB] = bv.x;  B[(lkB + 1) * 68 + lmB] = bv.y;
            B[(lkB + 2) * 68 + lmB] = bv.z;  B[(lkB + 3) * 68 + lmB] = bv.w;
        }
        if (t < 6) {
            a0 = *(const float4*)(xp + (t + 2) * 16);
            a1 = *(const float4*)(xp + (t + 2) * 16 + 4);
            bv = *(const float4*)(wp + (t + 2) * 16);
        }
        const float* A = As[t & 1]; const float* B = Bs[t & 1];
#pragma unroll
        for (int k = 0; k < 16; ++k) {
            const float4 r0 = *(const float4*)&A[k * 132 + ty * 8];
            const float4 r1 = *(const float4*)&A[k * 132 + ty * 8 + 4];
            const double2 b2 = *(const double2*)&B[k * 68 + tx * 4];
            double d;
            d = dup2(r0.x); acc[0][0] = fma2(d, b2.x, acc[0][0]);
                            acc[0][1] = fma2(d, b2.y, acc[0][1]);
            d = dup2(r0.y); acc[1][0] = fma2(d, b2.x, acc[1][0]);
                            acc[1][1] = fma2(d, b2.y, acc[1][1]);
            d = dup2(r0.z); acc[2][0] = fma2(d, b2.x, acc[2][0]);
                            acc[2][1] = fma2(d, b2.y, acc[2][1]);
            d = dup2(r0.w); acc[3][0] = fma2(d, b2.x, acc[3][0]);
                            acc[3][1] = fma2(d, b2.y, acc[3][1]);
            d = dup2(r1.x); acc[4][0] = fma2(d, b2.x, acc[4][0]);
                            acc[4][1] = fma2(d, b2.y, acc[4][1]);
            d = dup2(r1.y); acc[5][0] = fma2(d, b2.x, acc[5][0]);
                            acc[5][1] = fma2(d, b2.y, acc[5][1]);
            d = dup2(r1.z); acc[6][0] = fma2(d, b2.x, acc[6][0]);
                            acc[6][1] = fma2(d, b2.y, acc[6][1]);
            d = dup2(r1.w); acc[7][0] = fma2(d, b2.x, acc[7][0]);
                            acc[7][1] = fma2(d, b2.y, acc[7][1]);
        }
    }

    float* dst = g_part + (size_t)kh * NTOT * 512;
#pragma unroll
    for (int i = 0; i < 8; ++i) {
        const int row = g0 + ty * 8 + i;
        const float2 p0 = unpack2(acc[i][0]);
        const float2 p1 = unpack2(acc[i][1]);
        float4 o;
        if (kh == 0) {
            o.x = p0.x + bias[nw0 + tx * 4 + 0];
            o.y = p0.y + bias[nw0 + tx * 4 + 1];
            o.z = p1.x + bias[nw0 + tx * 4 + 2];
            o.w = p1.y + bias[nw0 + tx * 4 + 3];
        } else {
            o.x = p0.x; o.y = p0.y; o.z = p1.x; o.w = p1.y;
        }
        *(float4*)&dst[row * 512 + n0 + tx * 4] = o;
    }
}

// ---------------------------------------------------------------------------
// Kernel 2: finalize. Sum 2 K-partials -> g_xlxr; L/R dots; xr transpose g_xrT.
// ---------------------------------------------------------------------------
#define SLAB_S 524
#define FIN_SMEM ((32 * SLAB_S + 256) * 4)

__global__ __launch_bounds__(256) void finalize_kernel(const float* __restrict__ att)
{
    extern __shared__ float sh[];
    float* slab  = sh;                 // [32][SLAB_S]
    float* att_s = sh + 32 * SLAB_S;   // [256]
    const int tid = threadIdx.x;
    const int g0 = blockIdx.x * 32;
    const int b = g0 >> 9;
    const int j0b = g0 & 511;

    att_s[tid] = att[tid];
#pragma unroll
    for (int p = 0; p < 16; ++p) {
        const int idx = p * 256 + tid;
        const int row = idx >> 7, c4 = idx & 127;
        const size_t ga = (size_t)(g0 + row) * 512 + c4 * 4;
        float4 a = *(const float4*)&g_part[ga];
        const float4 c = *(const float4*)&g_part[(size_t)NTOT * 512 + ga];
        a.x += c.x; a.y += c.y; a.z += c.z; a.w += c.w;
        *(float4*)&g_xlxr[ga] = a;
        *(float4*)&slab[row * SLAB_S + c4 * 4] = a;
    }
    __syncthreads();

    const int w = tid >> 5, l = tid & 31;
#pragma unroll
    for (int p = 0; p < 8; ++p) {
        const int id = p * 8 + w;
        const int row = id >> 1, half = id & 1;
        float s = 0.f;
#pragma unroll
        for (int q = 0; q < 8; ++q)
            s += att_s[l + 32 * q] * slab[row * SLAB_S + half * 256 + l + 32 * q];
#pragma unroll
        for (int off = 16; off; off >>= 1) s += __shfl_xor_sync(0xffffffffu, s, off);
        if (l == 0) {
            if (half) g_R[g0 + row] = 0.6f * s;
            else      g_L[g0 + row] = 0.6f * s;
        }
    }

    // transpose xr half -> g_xrT[b][d][j]
#pragma unroll
    for (int p = 0; p < 32; ++p) {
        const int idx = p * 256 + tid;      // 0..8191
        const int d = idx >> 5, jl = idx & 31;
        g_xrT[((size_t)b * 256 + d) * 512 + j0b + jl] = slab[jl * SLAB_S + 256 + d];
    }
}

// ---------------------------------------------------------------------------
// Kernel 3: FUSED pairwise scores + top-20 + softmax.
// 128 threads, 4 i-rows, grid 512. Thread owns j-pairs {tid, tid+128} x 4 rows.
// xr LDGs register-double-buffered: chunk c+1 prefetched during chunk c.
// ---------------------------------------------------------------------------
__global__ __launch_bounds__(128, 5) void pairtop_kernel(const float* __restrict__ att,
                                                         float* __restrict__ out)
{
    __shared__ double xl2d[256 * 4];   // [d][r] dup'd xl, 8KB
    __shared__ double ws2[256];        // dup'd 0.4*att, 2KB
    __shared__ float  alpha_s[4 * 512];
    __shared__ float  Ls[4];

    const int tid = threadIdx.x;
    const int g0 = blockIdx.x * 4;
    const int b512 = g0 & ~511;
    const int b = b512 >> 9;

    ws2[tid]       = dup2(0.4f * att[tid]);
    ws2[tid + 128] = dup2(0.4f * att[tid + 128]);
    if (tid < 4) Ls[tid] = g_L[g0 + tid];
#pragma unroll
    for (int q = 0; q < 8; ++q) {
        const int idx = q * 128 + tid;     // 0..1023
        const int r = idx & 3, d = idx >> 2;
        xl2d[d * 4 + r] = dup2(g_xlxr[(size_t)(g0 + r) * 512 + d]);
    }
    __syncthreads();

    const int jp0 = tid;                   // j-pairs owned by this thread
    const int jp1 = tid + 128;
    const double* __restrict__ xrp =
        (const double*)g_xrT + (size_t)b * 256 * 256;
    const float2 Rj0 = *(const float2*)&g_R[b512 + 2 * jp0];
    const float2 Rj1 = *(const float2*)&g_R[b512 + 2 * jp1];

    double acc[8];                         // [row][jp]: acc[2r], acc[2r+1]
#pragma unroll
    for (int i = 0; i < 8; ++i) acc[i] = 0.0;

    // register double-buffer for xr chunks (4 d each)
    double xr0[2][4], xr1[2][4];
#pragma unroll
    for (int q = 0; q < 4; ++q) {
        xr0[0][q] = xrp[(size_t)q * 256 + jp0];
        xr1[0][q] = xrp[(size_t)q * 256 + jp1];
    }

#pragma unroll 2
    for (int c = 0; c < 64; ++c) {
        const int cur = c & 1, nxt = cur ^ 1;
        if (c < 63) {                       // prefetch next chunk's xr
#pragma unroll
            for (int q = 0; q < 4; ++q) {
                xr0[nxt][q] = xrp[(size_t)((c + 1) * 4 + q) * 256 + jp0];
                xr1[nxt][q] = xrp[(size_t)((c + 1) * 4 + q) * 256 + jp1];
            }
        }
#pragma unroll
        for (int q = 0; q < 4; ++q) {
            const int d = c * 4 + q;
            const double wsd = ws2[d];
            const double2 x01 = *(const double2*)&xl2d[d * 4 + 0];
            const double2 x23 = *(const double2*)&xl2d[d * 4 + 2];
            acc[0] = fma2(wsd, abs2(add2(x01.x, xr0[cur][q])), acc[0]);
            acc[1] = fma2(wsd, abs2(add2(x01.x, xr1[cur][q])), acc[1]);
            acc[2] = fma2(wsd, abs2(add2(x01.y, xr0[cur][q])), acc[2]);
            acc[3] = fma2(wsd, abs2(add2(x01.y, xr1[cur][q])), acc[3]);
            acc[4] = fma2(wsd, abs2(add2(x23.x, xr0[cur][q])), acc[4]);
            acc[5] = fma2(wsd, abs2(add2(x23.x, xr1[cur][q])), acc[5]);
            acc[6] = fma2(wsd, abs2(add2(x23.y, xr0[cur][q])), acc[6]);
            acc[7] = fma2(wsd, abs2(add2(x23.y, xr1[cur][q])), acc[7]);
        }
    }
#pragma unroll
    for (int r = 0; r < 4; ++r) {
        const float2 f0 = unpack2(acc[2 * r]);
        const float2 f1 = unpack2(acc[2 * r + 1]);
        *(float2*)&alpha_s[r * 512 + 2 * jp0] =
            make_float2(Ls[r] + Rj0.x + f0.x, Ls[r] + Rj0.y + f0.y);
        *(float2*)&alpha_s[r * 512 + 2 * jp1] =
            make_float2(Ls[r] + Rj1.x + f1.x, Ls[r] + Rj1.y + f1.y);
    }
    __syncthreads();

    // ---- top-20 + softmax: warp w handles row w (4 warps, 4 rows) ----
    const int w = tid >> 5, l = tid & 31;
    const float* arow = &alpha_s[w * 512];
    float v[16];
#pragma unroll
    for (int t = 0; t < 16; ++t) v[t] = arow[l + 32 * t];

    float wv = 0.f; int wj = 0;
    for (int kk = 0; kk < KSEL; ++kk) {
        float bv = -INFINITY; int bt = 0;
#pragma unroll
        for (int t = 0; t < 16; ++t)
            if (v[t] > bv) { bv = v[t]; bt = t; }   // strict > keeps lowest j
        int bj = bt * 32 + l;
#pragma unroll
        for (int off = 16; off; off >>= 1) {
            const float ov = __shfl_xor_sync(0xffffffffu, bv, off);
            const int   oj = __shfl_xor_sync(0xffffffffu, bj, off);
            if (ov > bv || (ov == bv && oj < bj)) { bv = ov; bj = oj; }
        }
        if (l == kk) { wv = bv; wj = bj; }
        const int owner = bj & 31, slot = bj >> 5;
        if (l == owner) {
#pragma unroll
            for (int t = 0; t < 16; ++t)
                if (slot == t) v[t] = -INFINITY;
        }
    }

    const float m = __shfl_sync(0xffffffffu, wv, 0);   // largest selected
    const float e = (l < KSEL) ? expf(wv - m) : 0.f;
    float s = e;
#pragma unroll
    for (int off = 16; off; off >>= 1) s += __shfl_xor_sync(0xffffffffu, s, off);
    if (l < KSEL) {
        const int g = g0 + w;
        const int base = g * KSEL + l;
        out[base]                   = (float)g;             // index_i
        out[NTOT * KSEL + base]     = (float)(b512 + wj);   // index_j
        out[2 * NTOT * KSEL + base] = e / s;                // attention
    }
}

// ---------------------------------------------------------------------------
extern "C" void kernel_launch(void* const* d_in, const int* in_sizes, int n_in,
                              void* d_out, int out_size)
{
    const float* x   = (const float*)d_in[0];
    const float* Wl  = (const float*)d_in[3];
    const float* bl  = (const float*)d_in[4];
    const float* Wr  = (const float*)d_in[5];
    const float* br  = (const float*)d_in[6];
    const float* att = (const float*)d_in[7];
    float* out = (float*)d_out;

    proj_kernel<<<dim3(16, 8, 2), 256>>>(x, Wl, bl, Wr, br);
    cudaFuncSetAttribute(finalize_kernel,
                         cudaFuncAttributeMaxDynamicSharedMemorySize, FIN_SMEM);
    finalize_kernel<<<64, 256, FIN_SMEM>>>(att);
    pairtop_kernel<<<512, 128>>>(att, out);
}

// round 10
// speedup vs baseline: 1.0523x; 1.0171x over previous
#include <cuda_runtime.h>
#include <math.h>

#define NTOT 2048          // B*N
#define KSEL 20

__device__ float  g_part[2 * NTOT * 512]; // K-split partial GEMM results
__device__ float  g_xlxr[NTOT * 512];     // [g][0:256)=xl, [256:512)=xr
__device__ float  g_xrT[4 * 256 * 512];   // [b][d][j] transposed xr
__device__ float  g_L[NTOT];
__device__ float  g_R[NTOT];

// ---------------- packed f32x2 helpers ----------------
__device__ __forceinline__ double fma2(double a, double b, double c) {
    double d;
    asm("fma.rn.f32x2 %0, %1, %2, %3;" : "=d"(d) : "d"(a), "d"(b), "d"(c));
    return d;
}
__device__ __forceinline__ double add2(double a, double b) {
    double d;
    asm("add.rn.f32x2 %0, %1, %2;" : "=d"(d) : "d"(a), "d"(b));
    return d;
}
__device__ __forceinline__ double abs2(double a) {
    return __longlong_as_double(__double_as_longlong(a) & 0x7fffffff7fffffffULL);
}
__device__ __forceinline__ double dup2(float v) {
    double d;
    asm("mov.b64 %0, {%1, %1};" : "=d"(d) : "f"(v));
    return d;
}
__device__ __forceinline__ float2 unpack2(double a) {
    float2 f;
    asm("mov.b64 {%0, %1}, %2;" : "=f"(f.x), "=f"(f.y) : "d"(a));
    return f;
}

// ---------------------------------------------------------------------------
// Kernel 1: K-split-2 projection GEMM. Tile 128(M) x 64(N), BK=16, K=128/blk,
// 256 threads, per-thread 8x4 (2 f32x2 pairs), A scalar-broadcast + reg-dup.
// grid (16, 8, 2) = 256 blocks.
// ---------------------------------------------------------------------------
__global__ __launch_bounds__(256, 3) void proj_kernel(
    const float* __restrict__ x,
    const float* __restrict__ Wl, const float* __restrict__ bl,
    const float* __restrict__ Wr, const float* __restrict__ br)
{
    __shared__ __align__(16) float As[2][16 * 132];  // [k][m], m=128 (+pad)
    __shared__ __align__(16) float Bs[2][16 * 68];   // [k][n], n=64 (+pad)
    const int tid = threadIdx.x;
    const int tx = tid & 15;          // N direction (4 cols each)
    const int ty = tid >> 4;          // M direction (8 rows each)
    const int g0 = blockIdx.x * 128;
    const int n0 = blockIdx.y * 64;
    const int kh = blockIdx.z;        // K half
    const float* W    = (n0 < 256) ? Wl : Wr;
    const float* bias = (n0 < 256) ? bl : br;
    const int nw0 = (n0 < 256) ? n0 : n0 - 256;

    const int lmA = tid >> 1;             // 0..127
    const int lkA = (tid & 1) * 8;        // 0 or 8
    const int lmB = tid >> 2;             // 0..63
    const int lkB = (tid & 3) * 4;        // 0,4,8,12

    const float* xp = &x[(g0 + lmA) * 256 + kh * 128 + lkA];
    const float* wp = &W[(nw0 + lmB) * 256 + kh * 128 + lkB];

    double acc[8][2];
#pragma unroll
    for (int i = 0; i < 8; ++i) { acc[i][0] = 0.0; acc[i][1] = 0.0; }

    float4 a0 = *(const float4*)xp;
    float4 a1 = *(const float4*)(xp + 4);
    float4 bv = *(const float4*)wp;
    {
        float* A = As[0]; float* B = Bs[0];
        A[(lkA + 0) * 132 + lmA] = a0.x; A[(lkA + 1) * 132 + lmA] = a0.y;
        A[(lkA + 2) * 132 + lmA] = a0.z; A[(lkA + 3) * 132 + lmA] = a0.w;
        A[(lkA + 4) * 132 + lmA] = a1.x; A[(lkA + 5) * 132 + lmA] = a1.y;
        A[(lkA + 6) * 132 + lmA] = a1.z; A[(lkA + 7) * 132 + lmA] = a1.w;
        B[(lkB + 0) * 68 + lmB] = bv.x;  B[(lkB + 1) * 68 + lmB] = bv.y;
        B[(lkB + 2) * 68 + lmB] = bv.z;  B[(lkB + 3) * 68 + lmB] = bv.w;
    }
    a0 = *(const float4*)(xp + 16);
    a1 = *(const float4*)(xp + 20);
    bv = *(const float4*)(wp + 16);

#pragma unroll 1
    for (int t = 0; t < 8; ++t) {
        __syncthreads();
        if (t < 7) {
            float* A = As[(t + 1) & 1]; float* B = Bs[(t + 1) & 1];
            A[(lkA + 0) * 132 + lmA] = a0.x; A[(lkA + 1) * 132 + lmA] = a0.y;
            A[(lkA + 2) * 132 + lmA] = a0.z; A[(lkA + 3) * 132 + lmA] = a0.w;
            A[(lkA + 4) * 132 + lmA] = a1.x; A[(lkA + 5) * 132 + lmA] = a1.y;
            A[(lkA + 6) * 132 + lmA] = a1.z; A[(lkA + 7) * 132 + lmA] = a1.w;
            B[(lkB + 0) * 68 + lmB] = bv.x;  B[(lkB + 1) * 68 + lmB] = bv.y;
            B[(lkB + 2) * 68 + lmB] = bv.z;  B[(lkB + 3) * 68 + lmB] = bv.w;
        }
        if (t < 6) {
            a0 = *(const float4*)(xp + (t + 2) * 16);
            a1 = *(const float4*)(xp + (t + 2) * 16 + 4);
            bv = *(const float4*)(wp + (t + 2) * 16);
        }
        const float* A = As[t & 1]; const float* B = Bs[t & 1];
#pragma unroll
        for (int k = 0; k < 16; ++k) {
            const float4 r0 = *(const float4*)&A[k * 132 + ty * 8];
            const float4 r1 = *(const float4*)&A[k * 132 + ty * 8 + 4];
            const double2 b2 = *(const double2*)&B[k * 68 + tx * 4];
            double d;
            d = dup2(r0.x); acc[0][0] = fma2(d, b2.x, acc[0][0]);
                            acc[0][1] = fma2(d, b2.y, acc[0][1]);
            d = dup2(r0.y); acc[1][0] = fma2(d, b2.x, acc[1][0]);
                            acc[1][1] = fma2(d, b2.y, acc[1][1]);
            d = dup2(r0.z); acc[2][0] = fma2(d, b2.x, acc[2][0]);
                            acc[2][1] = fma2(d, b2.y, acc[2][1]);
            d = dup2(r0.w); acc[3][0] = fma2(d, b2.x, acc[3][0]);
                            acc[3][1] = fma2(d, b2.y, acc[3][1]);
            d = dup2(r1.x); acc[4][0] = fma2(d, b2.x, acc[4][0]);
                            acc[4][1] = fma2(d, b2.y, acc[4][1]);
            d = dup2(r1.y); acc[5][0] = fma2(d, b2.x, acc[5][0]);
                            acc[5][1] = fma2(d, b2.y, acc[5][1]);
            d = dup2(r1.z); acc[6][0] = fma2(d, b2.x, acc[6][0]);
                            acc[6][1] = fma2(d, b2.y, acc[6][1]);
            d = dup2(r1.w); acc[7][0] = fma2(d, b2.x, acc[7][0]);
                            acc[7][1] = fma2(d, b2.y, acc[7][1]);
        }
    }

    float* dst = g_part + (size_t)kh * NTOT * 512;
#pragma unroll
    for (int i = 0; i < 8; ++i) {
        const int row = g0 + ty * 8 + i;
        const float2 p0 = unpack2(acc[i][0]);
        const float2 p1 = unpack2(acc[i][1]);
        float4 o;
        if (kh == 0) {
            o.x = p0.x + bias[nw0 + tx * 4 + 0];
            o.y = p0.y + bias[nw0 + tx * 4 + 1];
            o.z = p1.x + bias[nw0 + tx * 4 + 2];
            o.w = p1.y + bias[nw0 + tx * 4 + 3];
        } else {
            o.x = p0.x; o.y = p0.y; o.z = p1.x; o.w = p1.y;
        }
        *(float4*)&dst[row * 512 + n0 + tx * 4] = o;
    }
}

// ---------------------------------------------------------------------------
// Kernel 2: finalize. Sum 2 K-partials -> g_xlxr; L/R dots; xr transpose g_xrT.
// ---------------------------------------------------------------------------
#define SLAB_S 524
#define FIN_SMEM ((32 * SLAB_S + 256) * 4)

__global__ __launch_bounds__(256) void finalize_kernel(const float* __restrict__ att)
{
    extern __shared__ float sh[];
    float* slab  = sh;                 // [32][SLAB_S]
    float* att_s = sh + 32 * SLAB_S;   // [256]
    const int tid = threadIdx.x;
    const int g0 = blockIdx.x * 32;
    const int b = g0 >> 9;
    const int j0b = g0 & 511;

    att_s[tid] = att[tid];
#pragma unroll
    for (int p = 0; p < 16; ++p) {
        const int idx = p * 256 + tid;
        const int row = idx >> 7, c4 = idx & 127;
        const size_t ga = (size_t)(g0 + row) * 512 + c4 * 4;
        float4 a = *(const float4*)&g_part[ga];
        const float4 c = *(const float4*)&g_part[(size_t)NTOT * 512 + ga];
        a.x += c.x; a.y += c.y; a.z += c.z; a.w += c.w;
        *(float4*)&g_xlxr[ga] = a;
        *(float4*)&slab[row * SLAB_S + c4 * 4] = a;
    }
    __syncthreads();

    const int w = tid >> 5, l = tid & 31;
#pragma unroll
    for (int p = 0; p < 8; ++p) {
        const int id = p * 8 + w;
        const int row = id >> 1, half = id & 1;
        float s = 0.f;
#pragma unroll
        for (int q = 0; q < 8; ++q)
            s += att_s[l + 32 * q] * slab[row * SLAB_S + half * 256 + l + 32 * q];
#pragma unroll
        for (int off = 16; off; off >>= 1) s += __shfl_xor_sync(0xffffffffu, s, off);
        if (l == 0) {
            if (half) g_R[g0 + row] = 0.6f * s;
            else      g_L[g0 + row] = 0.6f * s;
        }
    }

    // transpose xr half -> g_xrT[b][d][j]
#pragma unroll
    for (int p = 0; p < 32; ++p) {
        const int idx = p * 256 + tid;      // 0..8191
        const int d = idx >> 5, jl = idx & 31;
        g_xrT[((size_t)b * 256 + d) * 512 + j0b + jl] = slab[jl * SLAB_S + 256 + d];
    }
}

// ---------------------------------------------------------------------------
// Kernel 3: FUSED pairwise scores + top-20 + softmax.
// 256 threads, 8 i-rows/block, grid 256. Thread owns ONE j-pair x 8 rows
// (8 packed accumulators). Halves L2 xr traffic vs 4-row blocks (128 MB).
// xr LDGs register-double-buffered. topk: warp w handles row w from smem.
// ---------------------------------------------------------------------------
__global__ __launch_bounds__(256, 3) void pairtop_kernel(const float* __restrict__ att,
                                                         float* __restrict__ out)
{
    __shared__ double xl2d[256 * 8];   // [d][r] dup'd xl, 16KB
    __shared__ double ws2[256];        // dup'd 0.4*att, 2KB
    __shared__ float  alpha_s[8 * 512];
    __shared__ float  Ls[8];

    const int tid = threadIdx.x;
    const int g0 = blockIdx.x * 8;
    const int b512 = g0 & ~511;
    const int b = b512 >> 9;

    ws2[tid] = dup2(0.4f * att[tid]);
    if (tid < 8) Ls[tid] = g_L[g0 + tid];
#pragma unroll
    for (int q = 0; q < 8; ++q) {
        const int idx = q * 256 + tid;     // 0..2047
        const int r = idx & 7, d = idx >> 3;
        xl2d[d * 8 + r] = dup2(g_xlxr[(size_t)(g0 + r) * 512 + d]);
    }
    __syncthreads();

    const int jp = tid;                    // j-pair: j = 2jp, 2jp+1
    const double* __restrict__ xrp =
        (const double*)g_xrT + (size_t)b * 256 * 256 + jp;
    const float2 Rj2 = *(const float2*)&g_R[b512 + 2 * jp];

    double acc[8];
#pragma unroll
    for (int i = 0; i < 8; ++i) acc[i] = 0.0;

    // register double-buffer for xr chunks (4 d each)
    double xr[2][4];
#pragma unroll
    for (int q = 0; q < 4; ++q) xr[0][q] = xrp[(size_t)q * 256];

#pragma unroll 2
    for (int c = 0; c < 64; ++c) {
        const int cur = c & 1, nxt = cur ^ 1;
        if (c < 63) {                       // prefetch next chunk's xr
#pragma unroll
            for (int q = 0; q < 4; ++q)
                xr[nxt][q] = xrp[(size_t)((c + 1) * 4 + q) * 256];
        }
#pragma unroll
        for (int q = 0; q < 4; ++q) {
            const int d = c * 4 + q;
            const double wsd = ws2[d];
            const double2 x01 = *(const double2*)&xl2d[d * 8 + 0];
            const double2 x23 = *(const double2*)&xl2d[d * 8 + 2];
            const double2 x45 = *(const double2*)&xl2d[d * 8 + 4];
            const double2 x67 = *(const double2*)&xl2d[d * 8 + 6];
            const double xv = xr[cur][q];
            acc[0] = fma2(wsd, abs2(add2(x01.x, xv)), acc[0]);
            acc[1] = fma2(wsd, abs2(add2(x01.y, xv)), acc[1]);
            acc[2] = fma2(wsd, abs2(add2(x23.x, xv)), acc[2]);
            acc[3] = fma2(wsd, abs2(add2(x23.y, xv)), acc[3]);
            acc[4] = fma2(wsd, abs2(add2(x45.x, xv)), acc[4]);
            acc[5] = fma2(wsd, abs2(add2(x45.y, xv)), acc[5]);
            acc[6] = fma2(wsd, abs2(add2(x67.x, xv)), acc[6]);
            acc[7] = fma2(wsd, abs2(add2(x67.y, xv)), acc[7]);
        }
    }
#pragma unroll
    for (int r = 0; r < 8; ++r) {
        const float2 f = unpack2(acc[r]);
        *(float2*)&alpha_s[r * 512 + 2 * jp] =
            make_float2(Ls[r] + Rj2.x + f.x, Ls[r] + Rj2.y + f.y);
    }
    __syncthreads();

    // ---- top-20 + softmax: warp w handles row w (8 warps, 8 rows) ----
    const int w = tid >> 5, l = tid & 31;
    const float* arow = &alpha_s[w * 512];
    float v[16];
#pragma unroll
    for (int t = 0; t < 16; ++t) v[t] = arow[l + 32 * t];

    float wv = 0.f; int wj = 0;
    for (int kk = 0; kk < KSEL; ++kk) {
        float bv = -INFINITY; int bt = 0;
#pragma unroll
        for (int t = 0; t < 16; ++t)
            if (v[t] > bv) { bv = v[t]; bt = t; }   // strict > keeps lowest j
        int bj = bt * 32 + l;
#pragma unroll
        for (int off = 16; off; off >>= 1) {
            const float ov = __shfl_xor_sync(0xffffffffu, bv, off);
            const int   oj = __shfl_xor_sync(0xffffffffu, bj, off);
            if (ov > bv || (ov == bv && oj < bj)) { bv = ov; bj = oj; }
        }
        if (l == kk) { wv = bv; wj = bj; }
        const int owner = bj & 31, slot = bj >> 5;
        if (l == owner) {
#pragma unroll
            for (int t = 0; t < 16; ++t)
                if (slot == t) v[t] = -INFINITY;
        }
    }

    const float m = __shfl_sync(0xffffffffu, wv, 0);   // largest selected
    const float e = (l < KSEL) ? expf(wv - m) : 0.f;
    float s = e;
#pragma unroll
    for (int off = 16; off; off >>= 1) s += __shfl_xor_sync(0xffffffffu, s, off);
    if (l < KSEL) {
        const int g = g0 + w;
        const int base = g * KSEL + l;
        out[base]                   = (float)g;             // index_i
        out[NTOT * KSEL + base]     = (float)(b512 + wj);   // index_j
        out[2 * NTOT * KSEL + base] = e / s;                // attention
    }
}

// ---------------------------------------------------------------------------
extern "C" void kernel_launch(void* const* d_in, const int* in_sizes, int n_in,
                              void* d_out, int out_size)
{
    const float* x   = (const float*)d_in[0];
    const float* Wl  = (const float*)d_in[3];
    const float* bl  = (const float*)d_in[4];
    const float* Wr  = (const float*)d_in[5];
    const float* br  = (const float*)d_in[6];
    const float* att = (const float*)d_in[7];
    float* out = (float*)d_out;

    proj_kernel<<<dim3(16, 8, 2), 256>>>(x, Wl, bl, Wr, br);
    cudaFuncSetAttribute(finalize_kernel,
                         cudaFuncAttributeMaxDynamicSharedMemorySize, FIN_SMEM);
    finalize_kernel<<<64, 256, FIN_SMEM>>>(att);
    pairtop_kernel<<<256, 256>>>(att, out);
}